// round 1
// baseline (speedup 1.0000x reference)
#include <cuda_runtime.h>

typedef unsigned long long u64;

#define Bn 16
#define Hn 1024
#define Tn 4096
#define CDn 8
#define CSn 1024

#define THREADS 128
#define TT 256
#define TILES_PER_B (Tn / TT)        // 16
#define NBLK (Bn * TILES_PER_B)      // 256

#define OUT_N ((size_t)Bn * Hn * Tn)                 // 67108864
#define LOSS_OFF (OUT_N)
#define IDX_OFF (OUT_N + 2)
#define PROJ_OFF (OUT_N + 2 + (size_t)Bn * Tn)

// scratch (__device__ globals: no allocations allowed)
__device__ float g_cbn[CSn * CDn];
__device__ float g_cbn2[CSn];
__device__ float g_losspart[NBLK];

__device__ __forceinline__ u64 pack2(float x, float y) {
    u64 r; asm("mov.b64 %0, {%1,%2};" : "=l"(r) : "f"(x), "f"(y)); return r;
}
__device__ __forceinline__ void unpack2(u64 v, float& x, float& y) {
    asm("mov.b64 {%0,%1}, %2;" : "=f"(x), "=f"(y) : "l"(v));
}
__device__ __forceinline__ u64 ffma2(u64 a, u64 b, u64 c) {
    u64 d; asm("fma.rn.f32x2 %0, %1, %2, %3;" : "=l"(d) : "l"(a), "l"(b), "l"(c)); return d;
}

// ---------------------------------------------------------------------------
// Prep: normalized codebook + its squared norms (match reference _l2_normalize)
// ---------------------------------------------------------------------------
__global__ void prep_kernel(const float* __restrict__ cb) {
    int j = blockIdx.x * blockDim.x + threadIdx.x;
    if (j >= CSn) return;
    float v[CDn];
#pragma unroll
    for (int d = 0; d < CDn; d++) v[d] = cb[j * CDn + d];
    float s = 0.f;
#pragma unroll
    for (int d = 0; d < CDn; d++) s = __fadd_rn(s, __fmul_rn(v[d], v[d]));
    float m = fmaxf(__fsqrt_rn(s), 1e-12f);
    float s2 = 0.f;
#pragma unroll
    for (int d = 0; d < CDn; d++) {
        float c = __fdiv_rn(v[d], m);
        g_cbn[j * CDn + d] = c;
        s2 = __fadd_rn(s2, __fmul_rn(c, c));
    }
    g_cbn2[j] = s2;
}

// ---------------------------------------------------------------------------
// Fused main: proj -> argmax(cos sim) -> quant/indices/proj/loss-partial -> out
// One block = one (batch, 256-t tile). Each thread owns 2 adjacent t columns.
// ---------------------------------------------------------------------------
extern __shared__ float smem[];

__global__ __launch_bounds__(THREADS) void main_kernel(
    const float* __restrict__ hid,   // [B,H,T]
    const float* __restrict__ w_in,  // [CD,H]
    const float* __restrict__ b_in,  // [CD]
    const float* __restrict__ w_out, // [H,CD]
    const float* __restrict__ b_out, // [H]
    const float* __restrict__ cb,    // [CS,CD]
    float* __restrict__ dout)
{
    float* ws   = smem;                 // [h][d]  in_proj_w transposed  (8192)
    float* cbs  = ws + Hn * CDn;        // [j][d]  normalized codebook   (8192)
    float* cb2s = cbs + CSn * CDn;      // [j]                           (1024)
    float* wos  = cb2s + CSn;           // [h][d]  out_proj_w            (8192)
    float* bos  = wos + Hn * CDn;       // [h]                           (1024)

    const int tid = threadIdx.x;

    for (int i = tid; i < Hn * CDn; i += THREADS) {
        int d = i >> 10, h = i & 1023;
        ws[h * CDn + d] = w_in[i];
    }
    for (int i = tid; i < CSn * CDn; i += THREADS) cbs[i] = g_cbn[i];
    for (int i = tid; i < CSn; i += THREADS)       cb2s[i] = g_cbn2[i];
    for (int i = tid; i < Hn * CDn; i += THREADS)  wos[i] = w_out[i];
    for (int i = tid; i < Hn; i += THREADS)        bos[i] = b_out[i];
    __syncthreads();

    const int blk  = blockIdx.x;
    const int b    = blk / TILES_PER_B;
    const int t0   = (blk % TILES_PER_B) * TT;
    const int tcol = t0 + 2 * tid;

    // ---------------- Phase 1: proj[d] for the 2 owned t columns -------------
    const float* xp = hid + (size_t)b * Hn * Tn + tcol;
    u64 acc0[4], acc1[4];
#pragma unroll
    for (int p = 0; p < 4; p++) { acc0[p] = 0ULL; acc1[p] = 0ULL; }

#pragma unroll 8
    for (int h = 0; h < Hn; h++) {
        float2 x = *reinterpret_cast<const float2*>(xp + (size_t)h * Tn);
        u64 x0 = pack2(x.x, x.x);
        u64 x1 = pack2(x.y, x.y);
        const u64* wr = reinterpret_cast<const u64*>(ws + h * CDn);
#pragma unroll
        for (int p = 0; p < 4; p++) {
            u64 w = wr[p];
            acc0[p] = ffma2(w, x0, acc0[p]);
            acc1[p] = ffma2(w, x1, acc1[p]);
        }
    }

    float p0[CDn], p1[CDn];
#pragma unroll
    for (int p = 0; p < 4; p++) {
        unpack2(acc0[p], p0[2 * p], p0[2 * p + 1]);
        unpack2(acc1[p], p1[2 * p], p1[2 * p + 1]);
    }
#pragma unroll
    for (int d = 0; d < CDn; d++) {
        float bb = __ldg(b_in + d);
        p0[d] = __fadd_rn(p0[d], bb);
        p1[d] = __fadd_rn(p1[d], bb);
    }

    // ---------------- Phase 2: normalize + cosine argmax ---------------------
    float l2r0 = 0.f, l2r1 = 0.f;
#pragma unroll
    for (int d = 0; d < CDn; d++) {
        l2r0 = __fadd_rn(l2r0, __fmul_rn(p0[d], p0[d]));
        l2r1 = __fadd_rn(l2r1, __fmul_rn(p1[d], p1[d]));
    }
    float den0 = fmaxf(__fsqrt_rn(l2r0), 1e-12f);
    float den1 = fmaxf(__fsqrt_rn(l2r1), 1e-12f);
    float e0[CDn], e1[CDn];
    float l20 = 0.f, l21 = 0.f;
#pragma unroll
    for (int d = 0; d < CDn; d++) {
        e0[d] = __fdiv_rn(p0[d], den0);
        e1[d] = __fdiv_rn(p1[d], den1);
        l20 = __fadd_rn(l20, __fmul_rn(e0[d], e0[d]));
        l21 = __fadd_rn(l21, __fmul_rn(e1[d], e1[d]));
    }

    u64 ed0[4], ed1[4];
#pragma unroll
    for (int p = 0; p < 4; p++) {
        ed0[p] = pack2(e0[2 * p], e0[2 * p + 1]);
        ed1[p] = pack2(e1[2 * p], e1[2 * p + 1]);
    }

    float best0 = -3.402823466e38f, best1 = -3.402823466e38f;
    int i0 = 0, i1 = 0;
#pragma unroll 2
    for (int j = 0; j < CSn; j++) {
        const u64* cr = reinterpret_cast<const u64*>(cbs + j * CDn);
        u64 c0 = cr[0], c1 = cr[1], c2 = cr[2], c3 = cr[3];
        float cb2 = cb2s[j];

        u64 a = ffma2(ed0[0], c0, 0ULL);
        a = ffma2(ed0[1], c1, a); a = ffma2(ed0[2], c2, a); a = ffma2(ed0[3], c3, a);
        float alo, ahi; unpack2(a, alo, ahi);
        float dot0 = __fadd_rn(alo, ahi);
        float s0 = __fsub_rn(cb2, __fmaf_rn(-2.f, dot0, l20));
        if (s0 > best0) { best0 = s0; i0 = j; }

        u64 bq = ffma2(ed1[0], c0, 0ULL);
        bq = ffma2(ed1[1], c1, bq); bq = ffma2(ed1[2], c2, bq); bq = ffma2(ed1[3], c3, bq);
        float blo, bhi; unpack2(bq, blo, bhi);
        float dot1 = __fadd_rn(blo, bhi);
        float s1 = __fsub_rn(cb2, __fmaf_rn(-2.f, dot1, l21));
        if (s1 > best1) { best1 = s1; i1 = j; }
    }

    // quant lookup (raw codebook, L1-hot 32KB)
    const float4* cbv = reinterpret_cast<const float4*>(cb);
    float4 qa0 = __ldg(cbv + i0 * 2), qb0 = __ldg(cbv + i0 * 2 + 1);
    float4 qa1 = __ldg(cbv + i1 * 2), qb1 = __ldg(cbv + i1 * 2 + 1);
    float q0[CDn] = {qa0.x, qa0.y, qa0.z, qa0.w, qb0.x, qb0.y, qb0.z, qb0.w};
    float q1[CDn] = {qa1.x, qa1.y, qa1.z, qa1.w, qb1.x, qb1.y, qb1.z, qb1.w};

    // loss partial, indices, proj writes
    float ls = 0.f;
#pragma unroll
    for (int d = 0; d < CDn; d++) {
        float a = p0[d] - q0[d]; ls = __fmaf_rn(a, a, ls);
        float c = p1[d] - q1[d]; ls = __fmaf_rn(c, c, ls);
    }
    *reinterpret_cast<float2*>(dout + IDX_OFF + (size_t)b * Tn + tcol) =
        make_float2((float)i0, (float)i1);
#pragma unroll
    for (int d = 0; d < CDn; d++) {
        *reinterpret_cast<float2*>(dout + PROJ_OFF + ((size_t)b * CDn + d) * Tn + tcol) =
            make_float2(p0[d], p1[d]);
    }

#pragma unroll
    for (int o = 16; o; o >>= 1) ls += __shfl_xor_sync(0xFFFFFFFFu, ls, o);
    __shared__ float wsum[THREADS / 32];
    if ((tid & 31) == 0) wsum[tid >> 5] = ls;
    __syncthreads();
    if (tid == 0) g_losspart[blk] = (wsum[0] + wsum[1]) + (wsum[2] + wsum[3]);

    // ---------------- Phase 3: out[h,t] = quant . Wout[h] + b_out[h] ---------
    u64 qp0[4], qp1[4];
#pragma unroll
    for (int p = 0; p < 4; p++) {
        qp0[p] = pack2(q0[2 * p], q0[2 * p + 1]);
        qp1[p] = pack2(q1[2 * p], q1[2 * p + 1]);
    }
    float* outbase = dout + (size_t)b * Hn * Tn + tcol;
#pragma unroll 4
    for (int h = 0; h < Hn; h++) {
        const u64* wr = reinterpret_cast<const u64*>(wos + h * CDn);
        u64 w0 = wr[0], w1 = wr[1], w2 = wr[2], w3 = wr[3];
        float bo = bos[h];

        u64 a = ffma2(qp0[0], w0, 0ULL);
        a = ffma2(qp0[1], w1, a); a = ffma2(qp0[2], w2, a); a = ffma2(qp0[3], w3, a);
        float alo, ahi; unpack2(a, alo, ahi);
        float o0 = __fadd_rn(__fadd_rn(alo, ahi), bo);

        u64 c = ffma2(qp1[0], w0, 0ULL);
        c = ffma2(qp1[1], w1, c); c = ffma2(qp1[2], w2, c); c = ffma2(qp1[3], w3, c);
        float clo, chi; unpack2(c, clo, chi);
        float o1 = __fadd_rn(__fadd_rn(clo, chi), bo);

        *reinterpret_cast<float2*>(outbase + (size_t)h * Tn) = make_float2(o0, o1);
    }
}

// ---------------------------------------------------------------------------
// Final deterministic loss reduce: mean over B*CD*T (=2^19, exact division)
// ---------------------------------------------------------------------------
__global__ void loss_kernel(float* __restrict__ dout) {
    __shared__ float sh[8];
    int tid = threadIdx.x;                 // 256 threads, NBLK = 256
    float v = g_losspart[tid];
#pragma unroll
    for (int o = 16; o; o >>= 1) v += __shfl_xor_sync(0xFFFFFFFFu, v, o);
    if ((tid & 31) == 0) sh[tid >> 5] = v;
    __syncthreads();
    if (tid == 0) {
        float tot = 0.f;
#pragma unroll
        for (int w = 0; w < 8; w++) tot += sh[w];
        float mean = tot * (1.0f / (float)(Bn * CDn * Tn));
        dout[LOSS_OFF]     = mean;  // commitment_loss
        dout[LOSS_OFF + 1] = mean;  // codebook_loss (numerically identical)
    }
}

// ---------------------------------------------------------------------------
extern "C" void kernel_launch(void* const* d_in, const int* in_sizes, int n_in,
                              void* d_out, int out_size) {
    const float* hid   = (const float*)d_in[0];
    const float* w_in  = (const float*)d_in[1];
    const float* b_in  = (const float*)d_in[2];
    const float* w_out = (const float*)d_in[3];
    const float* b_out = (const float*)d_in[4];
    const float* cb    = (const float*)d_in[5];
    float* dout = (float*)d_out;

    const int smem_bytes = (Hn * CDn + CSn * CDn + CSn + Hn * CDn + Hn) * 4; // 106496
    cudaFuncSetAttribute(main_kernel, cudaFuncAttributeMaxDynamicSharedMemorySize, smem_bytes);

    prep_kernel<<<1, 1024>>>(cb);
    main_kernel<<<NBLK, THREADS, smem_bytes>>>(hid, w_in, b_in, w_out, b_out, cb, dout);
    loss_kernel<<<1, 256>>>(dout);
}

// round 4
// speedup vs baseline: 1.1890x; 1.1890x over previous
#include <cuda_runtime.h>

typedef unsigned long long u64;

#define Bn 16
#define Hn 1024
#define Tn 4096
#define CDn 8
#define CSn 1024

#define THREADS 128
#define TT 128
#define TILES_PER_B (Tn / TT)        // 32
#define NBLK (Bn * TILES_PER_B)      // 512

#define OUT_N ((size_t)Bn * Hn * Tn)
#define LOSS_OFF (OUT_N)
#define IDX_OFF (OUT_N + 2)
#define PROJ_OFF (OUT_N + 2 + (size_t)Bn * Tn)

__device__ float g_losspart[NBLK];

__device__ __forceinline__ u64 pack2(float x, float y) {
    u64 r; asm("mov.b64 %0, {%1,%2};" : "=l"(r) : "f"(x), "f"(y)); return r;
}
__device__ __forceinline__ void unpack2(u64 v, float& x, float& y) {
    asm("mov.b64 {%0,%1}, %2;" : "=f"(x), "=f"(y) : "l"(v));
}
__device__ __forceinline__ u64 ffma2(u64 a, u64 b, u64 c) {
    u64 d; asm("fma.rn.f32x2 %0, %1, %2, %3;" : "=l"(d) : "l"(a), "l"(b), "l"(c)); return d;
}

// smem float layout:
//   [0,9216)      buf : ws(8192) | cbs(8192)+cb2s(1024) | wos(8192)+bos(1024)
//   [9216,10240)  xfer: proj handoff, 128 t x 8 d
//   [10240,10368) sbest (64 float2)
//   [10368,10496) sidx  (64 int2)
//   [10496,10498) wsum  (2 floats)
#define SMEM_FLOATS 10504
extern __shared__ float smem[];

__global__ __launch_bounds__(THREADS, 4) void main_kernel(
    const float* __restrict__ hid,   // [B,H,T]
    const float* __restrict__ w_in,  // [CD,H]
    const float* __restrict__ b_in,  // [CD]
    const float* __restrict__ w_out, // [H,CD]
    const float* __restrict__ b_out, // [H]
    const float* __restrict__ cb,    // [CS,CD]
    float* __restrict__ dout)
{
    float* buf   = smem;
    float* xfer  = smem + 9216;
    float2* sbest = reinterpret_cast<float2*>(smem + 10240);
    int2*   sidx  = reinterpret_cast<int2*>(smem + 10368);
    float*  wsum  = smem + 10496;

    const int tid = threadIdx.x;
    const int blk = blockIdx.x;
    const int b   = blk >> 5;
    const int t0  = (blk & 31) << 7;

    // ================= Phase 1: proj (1 t/thread, d-packed, full h) =========
    // fill ws[h][d] from w_in[d][h]
#pragma unroll
    for (int k = 0; k < 64; k++) {
        int idx = tid + THREADS * k;
        int d = idx >> 10, h = idx & 1023;
        buf[h * CDn + d] = w_in[idx];
    }
    __syncthreads();

    u64 acc[4] = {0ULL, 0ULL, 0ULL, 0ULL};
    {
        const float* xp = hid + (size_t)b * Hn * Tn + (t0 + tid);
#pragma unroll 8
        for (int h = 0; h < Hn; h++) {
            float x = xp[(size_t)h * Tn];
            u64 xd = pack2(x, x);
            const u64* wr = reinterpret_cast<const u64*>(buf + h * CDn);
            acc[0] = ffma2(wr[0], xd, acc[0]);
            acc[1] = ffma2(wr[1], xd, acc[1]);
            acc[2] = ffma2(wr[2], xd, acc[2]);
            acc[3] = ffma2(wr[3], xd, acc[3]);
        }
    }
    {
        float p[CDn];
#pragma unroll
        for (int q = 0; q < 4; q++) unpack2(acc[q], p[2 * q], p[2 * q + 1]);
#pragma unroll
        for (int d = 0; d < CDn; d++)
            xfer[tid * CDn + d] = __fadd_rn(p[d], __ldg(b_in + d));
    }
    __syncthreads();

    // ============ fill cbs (normalized codebook, same ops as old prep) ======
    float* cbs  = buf;
    float* cb2s = buf + CSn * CDn;
#pragma unroll
    for (int k = 0; k < 8; k++) {
        int j = tid + THREADS * k;
        const float4* cr = reinterpret_cast<const float4*>(cb + j * CDn);
        float4 ca = __ldg(cr), cbv4 = __ldg(cr + 1);
        float v[CDn] = {ca.x, ca.y, ca.z, ca.w, cbv4.x, cbv4.y, cbv4.z, cbv4.w};
        float s = 0.f;
#pragma unroll
        for (int d = 0; d < CDn; d++) s = __fadd_rn(s, __fmul_rn(v[d], v[d]));
        float m = fmaxf(__fsqrt_rn(s), 1e-12f);
        float cd[CDn];
        float s2 = 0.f;
#pragma unroll
        for (int d = 0; d < CDn; d++) {
            cd[d] = __fdiv_rn(v[d], m);
            s2 = __fadd_rn(s2, __fmul_rn(cd[d], cd[d]));
        }
        float4* dst = reinterpret_cast<float4*>(cbs + j * CDn);
        dst[0] = make_float4(cd[0], cd[1], cd[2], cd[3]);
        dst[1] = make_float4(cd[4], cd[5], cd[6], cd[7]);
        cb2s[j] = s2;
    }
    __syncthreads();

    // ================= Phase 2: argmax (2 t/thread, j split by warp-group) ==
    const int pr  = tid & 63;
    const int grp = tid >> 6;

    float p0[CDn], p1[CDn];
    {
        const float4* x0 = reinterpret_cast<const float4*>(xfer + (2 * pr) * CDn);
        const float4* x1 = reinterpret_cast<const float4*>(xfer + (2 * pr + 1) * CDn);
        float4 a0 = x0[0], a1 = x0[1], c0 = x1[0], c1 = x1[1];
        p0[0]=a0.x; p0[1]=a0.y; p0[2]=a0.z; p0[3]=a0.w;
        p0[4]=a1.x; p0[5]=a1.y; p0[6]=a1.z; p0[7]=a1.w;
        p1[0]=c0.x; p1[1]=c0.y; p1[2]=c0.z; p1[3]=c0.w;
        p1[4]=c1.x; p1[5]=c1.y; p1[6]=c1.z; p1[7]=c1.w;
    }

    float l2r0 = 0.f, l2r1 = 0.f;
#pragma unroll
    for (int d = 0; d < CDn; d++) {
        l2r0 = __fadd_rn(l2r0, __fmul_rn(p0[d], p0[d]));
        l2r1 = __fadd_rn(l2r1, __fmul_rn(p1[d], p1[d]));
    }
    float den0 = fmaxf(__fsqrt_rn(l2r0), 1e-12f);
    float den1 = fmaxf(__fsqrt_rn(l2r1), 1e-12f);
    float e0[CDn], e1[CDn];
    float l20 = 0.f, l21 = 0.f;
#pragma unroll
    for (int d = 0; d < CDn; d++) {
        e0[d] = __fdiv_rn(p0[d], den0);
        e1[d] = __fdiv_rn(p1[d], den1);
        l20 = __fadd_rn(l20, __fmul_rn(e0[d], e0[d]));
        l21 = __fadd_rn(l21, __fmul_rn(e1[d], e1[d]));
    }

    u64 ed0[4], ed1[4];
#pragma unroll
    for (int q = 0; q < 4; q++) {
        ed0[q] = pack2(e0[2 * q], e0[2 * q + 1]);
        ed1[q] = pack2(e1[2 * q], e1[2 * q + 1]);
    }

    const int jstart = grp << 9;
    float best0 = -3.402823466e38f, best1 = -3.402823466e38f;
    int i0 = jstart, i1 = jstart;
#pragma unroll 2
    for (int j = jstart; j < jstart + 512; j++) {
        const u64* cr = reinterpret_cast<const u64*>(cbs + j * CDn);
        u64 c0 = cr[0], c1 = cr[1], c2 = cr[2], c3 = cr[3];
        float cb2 = cb2s[j];

        u64 a = ffma2(ed0[0], c0, 0ULL);
        a = ffma2(ed0[1], c1, a); a = ffma2(ed0[2], c2, a); a = ffma2(ed0[3], c3, a);
        float alo, ahi; unpack2(a, alo, ahi);
        float dot0 = __fadd_rn(alo, ahi);
        float s0 = __fsub_rn(cb2, __fmaf_rn(-2.f, dot0, l20));
        if (s0 > best0) { best0 = s0; i0 = j; }

        u64 bq = ffma2(ed1[0], c0, 0ULL);
        bq = ffma2(ed1[1], c1, bq); bq = ffma2(ed1[2], c2, bq); bq = ffma2(ed1[3], c3, bq);
        float blo, bhi; unpack2(bq, blo, bhi);
        float dot1 = __fadd_rn(blo, bhi);
        float s1 = __fsub_rn(cb2, __fmaf_rn(-2.f, dot1, l21));
        if (s1 > best1) { best1 = s1; i1 = j; }
    }
    if (grp) {
        sbest[pr] = make_float2(best0, best1);
        sidx[pr]  = make_int2(i0, i1);
    }
    __syncthreads();

    // ======== fill wos/bos (all threads) + group0 combine & epilogue ========
    float* wos = buf;
    float* bos = buf + Hn * CDn;
    {
        const float4* wov = reinterpret_cast<const float4*>(w_out);
        float4* wod = reinterpret_cast<float4*>(wos);
#pragma unroll
        for (int k = 0; k < 16; k++) {
            int idx = tid + THREADS * k;
            wod[idx] = __ldg(wov + idx);
        }
#pragma unroll
        for (int k = 0; k < 8; k++) {
            int idx = tid + THREADS * k;
            bos[idx] = b_out[idx];
        }
    }

    if (grp == 0) {
        float2 bb = sbest[pr];
        int2   ii = sidx[pr];
        if (bb.x > best0) { best0 = bb.x; i0 = ii.x; }
        if (bb.y > best1) { best1 = bb.y; i1 = ii.y; }
        sidx[pr] = make_int2(i0, i1);

        *reinterpret_cast<float2*>(dout + IDX_OFF + (size_t)b * Tn + t0 + 2 * pr) =
            make_float2((float)i0, (float)i1);
#pragma unroll
        for (int d = 0; d < CDn; d++) {
            *reinterpret_cast<float2*>(dout + PROJ_OFF + ((size_t)b * CDn + d) * Tn + t0 + 2 * pr) =
                make_float2(p0[d], p1[d]);
        }

        const float4* cbv = reinterpret_cast<const float4*>(cb);
        float4 qa0 = __ldg(cbv + i0 * 2), qb0 = __ldg(cbv + i0 * 2 + 1);
        float4 qa1 = __ldg(cbv + i1 * 2), qb1 = __ldg(cbv + i1 * 2 + 1);
        float q0[CDn] = {qa0.x, qa0.y, qa0.z, qa0.w, qb0.x, qb0.y, qb0.z, qb0.w};
        float q1[CDn] = {qa1.x, qa1.y, qa1.z, qa1.w, qb1.x, qb1.y, qb1.z, qb1.w};

        float ls = 0.f;
#pragma unroll
        for (int d = 0; d < CDn; d++) {
            float a = p0[d] - q0[d]; ls = __fmaf_rn(a, a, ls);
            float c = p1[d] - q1[d]; ls = __fmaf_rn(c, c, ls);
        }
#pragma unroll
        for (int o = 16; o; o >>= 1) ls += __shfl_xor_sync(0xFFFFFFFFu, ls, o);
        if ((tid & 31) == 0) wsum[tid >> 5] = ls;
    }
    __syncthreads();
    if (tid == 0) g_losspart[blk] = wsum[0] + wsum[1];

    // ================= Phase 3: out (2 t/thread, h split by warp-group) =====
    int2 ji = sidx[pr];
    const float4* cbv = reinterpret_cast<const float4*>(cb);
    float4 qa0 = __ldg(cbv + ji.x * 2), qb0 = __ldg(cbv + ji.x * 2 + 1);
    float4 qa1 = __ldg(cbv + ji.y * 2), qb1 = __ldg(cbv + ji.y * 2 + 1);

    u64 qp0[4], qp1[4];
    qp0[0] = pack2(qa0.x, qa0.y); qp0[1] = pack2(qa0.z, qa0.w);
    qp0[2] = pack2(qb0.x, qb0.y); qp0[3] = pack2(qb0.z, qb0.w);
    qp1[0] = pack2(qa1.x, qa1.y); qp1[1] = pack2(qa1.z, qa1.w);
    qp1[2] = pack2(qb1.x, qb1.y); qp1[3] = pack2(qb1.z, qb1.w);

    float* outbase = dout + (size_t)b * Hn * Tn + (t0 + 2 * pr);
    const int hbase = grp << 9;
#pragma unroll 4
    for (int hh = 0; hh < 512; hh++) {
        int h = hbase + hh;
        const u64* wr = reinterpret_cast<const u64*>(wos + h * CDn);
        u64 w0 = wr[0], w1 = wr[1], w2 = wr[2], w3 = wr[3];
        float bo = bos[h];

        u64 a = ffma2(qp0[0], w0, 0ULL);
        a = ffma2(qp0[1], w1, a); a = ffma2(qp0[2], w2, a); a = ffma2(qp0[3], w3, a);
        float alo, ahi; unpack2(a, alo, ahi);
        float o0 = __fadd_rn(__fadd_rn(alo, ahi), bo);

        u64 c = ffma2(qp1[0], w0, 0ULL);
        c = ffma2(qp1[1], w1, c); c = ffma2(qp1[2], w2, c); c = ffma2(qp1[3], w3, c);
        float clo, chi; unpack2(c, clo, chi);
        float o1 = __fadd_rn(__fadd_rn(clo, chi), bo);

        *reinterpret_cast<float2*>(outbase + (size_t)h * Tn) = make_float2(o0, o1);
    }
}

// ---------------------------------------------------------------------------
__global__ void loss_kernel(float* __restrict__ dout) {
    __shared__ float sh[16];
    int tid = threadIdx.x;               // 512 threads, NBLK = 512
    float v = g_losspart[tid];
#pragma unroll
    for (int o = 16; o; o >>= 1) v += __shfl_xor_sync(0xFFFFFFFFu, v, o);
    if ((tid & 31) == 0) sh[tid >> 5] = v;
    __syncthreads();
    if (tid == 0) {
        float tot = 0.f;
#pragma unroll
        for (int w = 0; w < 16; w++) tot += sh[w];
        float mean = tot * (1.0f / (float)(Bn * CDn * Tn));
        dout[LOSS_OFF]     = mean;
        dout[LOSS_OFF + 1] = mean;
    }
}

// ---------------------------------------------------------------------------
extern "C" void kernel_launch(void* const* d_in, const int* in_sizes, int n_in,
                              void* d_out, int out_size) {
    const float* hid   = (const float*)d_in[0];
    const float* w_in  = (const float*)d_in[1];
    const float* b_in  = (const float*)d_in[2];
    const float* w_out = (const float*)d_in[3];
    const float* b_out = (const float*)d_in[4];
    const float* cb    = (const float*)d_in[5];
    float* dout = (float*)d_out;

    const int smem_bytes = SMEM_FLOATS * 4;  // 42016 B
    cudaFuncSetAttribute(main_kernel, cudaFuncAttributeMaxDynamicSharedMemorySize, smem_bytes);

    main_kernel<<<NBLK, THREADS, smem_bytes>>>(hid, w_in, b_in, w_out, b_out, cb, dout);
    loss_kernel<<<1, NBLK>>>(dout);
}